// round 8
// baseline (speedup 1.0000x reference)
#include <cuda_runtime.h>
#include <cuda_fp16.h>
#include <math.h>
#include <stdint.h>

#define NPTS 8192
#define NSRC 4096
#define DIM  256
#define TILE 128
#define NT   (NPTS / TILE)          // 64
#define NBLK (NT * (NT + 1) / 2)    // 2080 upper-triangle tile pairs

// ---------------------------------------------------------------- scratch
__device__ float  g_sq[NPTS];
__device__ double g_colsum[DIM];
__device__ double g_sumsq;
__device__ float  g_c;              // exp2 scale: -1/(16*bw'*ln2)
__device__ double g_acc;
__device__ __half g_hi[NPTS * DIM];
__device__ __half g_lo[NPTS * DIM];

// ---------------------------------------------------------------- helpers
__device__ __forceinline__ uint32_t smem_u32(const void* p) {
    uint32_t a;
    asm("{ .reg .u64 t; cvta.to.shared.u64 t, %1; cvt.u32.u64 %0, t; }" : "=r"(a) : "l"(p));
    return a;
}
#define CP_ASYNC16(dst, src) \
    asm volatile("cp.async.ca.shared.global [%0], [%1], 16;" :: "r"(dst), "l"(src))
#define CP_COMMIT() asm volatile("cp.async.commit_group;" ::: "memory")
#define CP_WAIT1()  asm volatile("cp.async.wait_group 1;" ::: "memory")

#define LDSM_X4(r0, r1, r2, r3, a) \
    asm volatile("ldmatrix.sync.aligned.m8n8.x4.shared.b16 {%0,%1,%2,%3}, [%4];" \
        : "=r"(r0), "=r"(r1), "=r"(r2), "=r"(r3) : "r"(a))

#define MMA_F16(d, a, b0, b1) \
    asm volatile("mma.sync.aligned.m16n8k16.row.col.f32.f16.f16.f32 " \
        "{%0,%1,%2,%3}, {%4,%5,%6,%7}, {%8,%9}, {%0,%1,%2,%3};" \
        : "+f"((d)[0]), "+f"((d)[1]), "+f"((d)[2]), "+f"((d)[3]) \
        : "r"((a)[0]), "r"((a)[1]), "r"((a)[2]), "r"((a)[3]), "r"(b0), "r"(b1))

__device__ __forceinline__ const float* row_ptr(const float* src, const float* tgt, int i) {
    return (i < NSRC) ? (src + (size_t)i * DIM) : (tgt + (size_t)(i - NSRC) * DIM);
}

// ---------------------------------------------------------------- prep kernels
__global__ void zero_kernel() {
    int t = threadIdx.x;
    if (t < DIM) g_colsum[t] = 0.0;
    if (t == 0) { g_sumsq = 0.0; g_acc = 0.0; }
}

// 128 blocks x 256 threads; block handles 64 rows (warp -> 8 rows).
// Fused: fp16 hi/lo split + per-row ||x||^2 + column sums.
__global__ void prep_kernel(const float* __restrict__ src, const float* __restrict__ tgt) {
    __shared__ float cs[DIM];
    int tid  = threadIdx.x;
    int wid  = tid >> 5;
    int lane = tid & 31;
    cs[tid] = 0.f;
    __syncthreads();

    float col_acc[8] = {0, 0, 0, 0, 0, 0, 0, 0};
    float sq_acc = 0.f;

    int rbase = blockIdx.x * 64 + wid * 8;
    for (int rr = 0; rr < 8; rr++) {
        int row = rbase + rr;
        const float4* p4 = (const float4*)row_ptr(src, tgt, row);
        float s = 0.f;
#pragma unroll
        for (int t = 0; t < 2; t++) {
            float4 v = p4[lane + t * 32];
            float x[4] = {v.x, v.y, v.z, v.w};
            uint32_t hb[4], lb[4];
#pragma unroll
            for (int k = 0; k < 4; k++) {
                s += x[k] * x[k];
                col_acc[t * 4 + k] += x[k];
                __half h = __float2half_rn(x[k]);
                float r = x[k] - __half2float(h);
                __half l = __float2half_rn(r);
                hb[k] = (uint32_t)__half_as_ushort(h);
                lb[k] = (uint32_t)__half_as_ushort(l);
            }
            size_t q = (size_t)row * 64 + lane + t * 32;   // uint2 index (4 halves)
            ((uint2*)g_hi)[q] = make_uint2(hb[0] | (hb[1] << 16), hb[2] | (hb[3] << 16));
            ((uint2*)g_lo)[q] = make_uint2(lb[0] | (lb[1] << 16), lb[2] | (lb[3] << 16));
        }
#pragma unroll
        for (int o = 16; o > 0; o >>= 1) s += __shfl_xor_sync(0xffffffffu, s, o);
        if (lane == 0) { g_sq[row] = s; sq_acc += s; }
    }
    if (lane == 0) atomicAdd(&g_sumsq, (double)sq_acc);

#pragma unroll
    for (int t = 0; t < 2; t++)
#pragma unroll
        for (int k = 0; k < 4; k++)
            atomicAdd(&cs[t * 128 + lane * 4 + k], col_acc[t * 4 + k]);
    __syncthreads();
    atomicAdd(&g_colsum[tid], (double)cs[tid]);
}

__global__ void finalize_kernel() {
    __shared__ double red[DIM];
    int t = threadIdx.x;
    double c = g_colsum[t];
    red[t] = c * c;
    __syncthreads();
    for (int o = 128; o > 0; o >>= 1) {
        if (t < o) red[t] += red[t + o];
        __syncthreads();
    }
    if (t == 0) {
        double n = (double)NPTS;
        double sumL2 = 2.0 * n * g_sumsq - 2.0 * red[0];
        double bw = sumL2 / (n * n - n) / 4.0;   // / KERNEL_MUL^(KERNEL_NUM//2)
        g_c = (float)(-1.0 / (16.0 * bw * 0.6931471805599453));
    }
}

// ---------------------------------------------------------------- main tile kernel
// 128 threads, 4 warps (2x2), warp tile 64x64, CTA tile 128x128; 2 CTAs/SM.
// smem arrays per stage: A_hi, B_hi, B_lo; each 128 rows x 80B (32 fp16 + pad)
#define STRIDE_B    80
#define ARR_BYTES   (128 * STRIDE_B)        // 10240
#define STAGE_BYTES (3 * ARR_BYTES)         // 30720
#define NSTAGE      3
#define DYN_SMEM    (NSTAGE * STAGE_BYTES)  // 92160

__global__ void __launch_bounds__(128, 2)
mmd_mma_kernel() {
    extern __shared__ char dsmem[];
    __shared__ float red[128];
    __shared__ float sqa_s[TILE];
    __shared__ float sqb_s[TILE];

    uint32_t dyn_u = smem_u32(dsmem);
    int tid  = threadIdx.x;
    int wid  = tid >> 5;
    int lane = tid & 31;
    int wm   = wid & 1;       // 2 warp-rows of 64
    int wn   = wid >> 1;      // 2 warp-cols of 64

    // decode linear block id -> (bi, bj), bi <= bj
    int b = blockIdx.x;
    float fb = (float)b;
    int bi = (int)((2.0f * NT + 1.0f - sqrtf((2.0f * NT + 1.0f) * (2.0f * NT + 1.0f) - 8.0f * fb)) * 0.5f);
    if (bi < 0) bi = 0;
    if (bi >= NT) bi = NT - 1;
#define TRI_START(i) ((i) * NT - (i) * ((i) - 1) / 2)
    while (bi + 1 < NT && TRI_START(bi + 1) <= b) bi++;
    while (bi > 0 && TRI_START(bi) > b) bi--;
    int bj = bi + (b - TRI_START(bi));
#undef TRI_START
    int row0 = bi * TILE;
    int col0 = bj * TILE;

    sqa_s[tid] = g_sq[row0 + tid];
    sqb_s[tid] = g_sq[col0 + tid];

    const char* gbase[3];
    gbase[0] = (const char*)(g_hi + (size_t)row0 * DIM);   // A_hi
    gbase[1] = (const char*)(g_hi + (size_t)col0 * DIM);   // B_hi
    gbase[2] = (const char*)(g_lo + (size_t)col0 * DIM);   // B_lo

    float acc[4][8][4];
#pragma unroll
    for (int mi = 0; mi < 4; mi++)
#pragma unroll
        for (int ni = 0; ni < 8; ni++)
#pragma unroll
            for (int e = 0; e < 4; e++) acc[mi][ni][e] = 0.f;

    // loader: 1536 x 16B per chunk; 128 threads -> 12 each
#define ISSUE_LOADS(c, s) do { \
    _Pragma("unroll") \
    for (int i = 0; i < 12; i++) { \
        int arr = i >> 2; \
        int rem = tid + (i & 3) * 128;      /* 0..511 */ \
        int row = rem >> 2; \
        int q   = rem & 3; \
        const char* srcp = gbase[arr] + (size_t)row * 512 + (c) * 64 + q * 16; \
        uint32_t dst = dyn_u + (s) * STAGE_BYTES + arr * ARR_BYTES + row * STRIDE_B + q * 16; \
        CP_ASYNC16(dst, srcp); \
    } \
    CP_COMMIT(); \
} while (0)

    // ldmatrix lane-address components
    int a_m    = lane >> 3;
    int a_rofs = ((a_m & 1) << 3) + (lane & 7);
    int a_koff = (a_m >> 1) << 4;
    int b_nofs = ((a_m >> 1) << 3) + (lane & 7);
    int b_koff = (a_m & 1) << 4;

    ISSUE_LOADS(0, 0);
    ISSUE_LOADS(1, 1);

    for (int c = 0; c < 8; c++) {
        int s = c % NSTAGE;
        CP_WAIT1();
        __syncthreads();      // all warps past chunk c-1 compute; stage (c+2)%3 free
        if (c + 2 < 8) ISSUE_LOADS(c + 2, (c + 2) % NSTAGE);

        uint32_t stage_u = dyn_u + s * STAGE_BYTES;
#pragma unroll
        for (int ks = 0; ks < 2; ks++) {
            uint32_t Ah[4][4], Bh[4][4], Bl[4][4];
#pragma unroll
            for (int mi = 0; mi < 4; mi++) {
                int r = wm * 64 + mi * 16 + a_rofs;
                uint32_t ad = stage_u + r * STRIDE_B + ks * 32 + a_koff;
                LDSM_X4(Ah[mi][0], Ah[mi][1], Ah[mi][2], Ah[mi][3], ad);
            }
#pragma unroll
            for (int pi = 0; pi < 4; pi++) {
                int nl = wn * 64 + pi * 16 + b_nofs;
                uint32_t bd = stage_u + ARR_BYTES + nl * STRIDE_B + ks * 32 + b_koff;
                LDSM_X4(Bh[pi][0], Bh[pi][1], Bh[pi][2], Bh[pi][3], bd);
                LDSM_X4(Bl[pi][0], Bl[pi][1], Bl[pi][2], Bl[pi][3], bd + ARR_BYTES);
            }
#pragma unroll
            for (int mi = 0; mi < 4; mi++) {
#pragma unroll
                for (int ni = 0; ni < 8; ni++) {
                    int pi = ni >> 1, h = (ni & 1) * 2;
                    MMA_F16(acc[mi][ni], Ah[mi], Bh[pi][h], Bh[pi][h + 1]);
                    MMA_F16(acc[mi][ni], Ah[mi], Bl[pi][h], Bl[pi][h + 1]);
                }
            }
        }
        // no trailing sync: next chunk's top barrier orders reads before refill
    }

    // epilogue: row = wm*64+mi*16 + lane/4 + (e>=2)*8 ; col = wn*64+ni*8 + (lane%4)*2 + (e&1)
    float cexp = g_c;
    int rlo = lane >> 2;
    int cl0 = (lane & 3) * 2;
    float s = 0.f;
#pragma unroll
    for (int mi = 0; mi < 4; mi++) {
        float sqr0 = sqa_s[wm * 64 + mi * 16 + rlo];
        float sqr1 = sqa_s[wm * 64 + mi * 16 + rlo + 8];
#pragma unroll
        for (int ni = 0; ni < 8; ni++) {
            float sqc0 = sqb_s[wn * 64 + ni * 8 + cl0];
            float sqc1 = sqb_s[wn * 64 + ni * 8 + cl0 + 1];
#pragma unroll
            for (int e = 0; e < 4; e++) {
                float sr = (e >= 2) ? sqr1 : sqr0;
                float sc = (e & 1) ? sqc1 : sqc0;
                float L2 = fmaxf(sr + sc - 2.f * acc[mi][ni][e], 0.f);
                float u;
                asm("ex2.approx.ftz.f32 %0, %1;" : "=f"(u) : "f"(L2 * cexp));
                float u2 = u * u, u4 = u2 * u2, u8 = u4 * u4;
                s += u + u2 + u4 + u8 + u8 * u8;
            }
        }
    }

    __syncthreads();
    red[tid] = s;
    __syncthreads();
#pragma unroll
    for (int o = 64; o > 0; o >>= 1) {
        if (tid < o) red[tid] += red[tid + o];
        __syncthreads();
    }
    if (tid == 0) {
        float w  = (bi == bj) ? 1.f : 2.f;
        float sr = (row0 < NSRC) ? 1.f : -1.f;
        float sc = (col0 < NSRC) ? 1.f : -1.f;
        atomicAdd(&g_acc, (double)(red[0] * w * sr * sc));
    }
}

__global__ void writeout_kernel(float* out) {
    out[0] = (float)(g_acc / ((double)NSRC * (double)NSRC));
}

// ---------------------------------------------------------------- launch
extern "C" void kernel_launch(void* const* d_in, const int* in_sizes, int n_in,
                              void* d_out, int out_size) {
    const float* src = (const float*)d_in[0];
    const float* tgt = (const float*)d_in[1];
    float* out = (float*)d_out;

    cudaFuncSetAttribute(mmd_mma_kernel, cudaFuncAttributeMaxDynamicSharedMemorySize, DYN_SMEM);

    zero_kernel<<<1, 256>>>();
    prep_kernel<<<NPTS / 64, 256>>>(src, tgt);     // split + norms + colsums fused
    finalize_kernel<<<1, 256>>>();
    mmd_mma_kernel<<<NBLK, 128, DYN_SMEM>>>();
    writeout_kernel<<<1, 1>>>(out);
}

// round 9
// speedup vs baseline: 1.4837x; 1.4837x over previous
#include <cuda_runtime.h>
#include <cuda_fp16.h>
#include <math.h>
#include <stdint.h>

#define NPTS 8192
#define NSRC 4096
#define DIM  256
#define TILE 128
#define NT   (NPTS / TILE)          // 64
#define NBLK (NT * (NT + 1) / 2)    // 2080 upper-triangle tile pairs

// ---------------------------------------------------------------- scratch
__device__ float  g_sq[NPTS];
__device__ double g_colsum[DIM];
__device__ double g_sumsq;
__device__ float  g_c;              // exp2 scale: -1/(16*bw'*ln2)
__device__ double g_acc;
__device__ __half g_h[NPTS * DIM];

// ---------------------------------------------------------------- helpers
__device__ __forceinline__ uint32_t smem_u32(const void* p) {
    uint32_t a;
    asm("{ .reg .u64 t; cvta.to.shared.u64 t, %1; cvt.u32.u64 %0, t; }" : "=r"(a) : "l"(p));
    return a;
}
#define CP_ASYNC16(dst, src) \
    asm volatile("cp.async.ca.shared.global [%0], [%1], 16;" :: "r"(dst), "l"(src))
#define CP_COMMIT() asm volatile("cp.async.commit_group;" ::: "memory")
#define CP_WAIT2()  asm volatile("cp.async.wait_group 2;" ::: "memory")

#define LDSM_X4(r0, r1, r2, r3, a) \
    asm volatile("ldmatrix.sync.aligned.m8n8.x4.shared.b16 {%0,%1,%2,%3}, [%4];" \
        : "=r"(r0), "=r"(r1), "=r"(r2), "=r"(r3) : "r"(a))

#define MMA_F16(d, a, b0, b1) \
    asm volatile("mma.sync.aligned.m16n8k16.row.col.f32.f16.f16.f32 " \
        "{%0,%1,%2,%3}, {%4,%5,%6,%7}, {%8,%9}, {%0,%1,%2,%3};" \
        : "+f"((d)[0]), "+f"((d)[1]), "+f"((d)[2]), "+f"((d)[3]) \
        : "r"((a)[0]), "r"((a)[1]), "r"((a)[2]), "r"((a)[3]), "r"(b0), "r"(b1))

__device__ __forceinline__ const float* row_ptr(const float* src, const float* tgt, int i) {
    return (i < NSRC) ? (src + (size_t)i * DIM) : (tgt + (size_t)(i - NSRC) * DIM);
}

// ---------------------------------------------------------------- prep kernels
__global__ void zero_kernel() {
    int t = threadIdx.x;
    if (t < DIM) g_colsum[t] = 0.0;
    if (t == 0) { g_sumsq = 0.0; g_acc = 0.0; }
}

// 128 blocks x 256 threads; block handles 64 rows (warp -> 8 rows).
// Fused: fp16 convert + per-row ||x||^2 + column sums.
__global__ void prep_kernel(const float* __restrict__ src, const float* __restrict__ tgt) {
    __shared__ float cs[DIM];
    int tid  = threadIdx.x;
    int wid  = tid >> 5;
    int lane = tid & 31;
    cs[tid] = 0.f;
    __syncthreads();

    float col_acc[8] = {0, 0, 0, 0, 0, 0, 0, 0};
    float sq_acc = 0.f;

    int rbase = blockIdx.x * 64 + wid * 8;
    for (int rr = 0; rr < 8; rr++) {
        int row = rbase + rr;
        const float4* p4 = (const float4*)row_ptr(src, tgt, row);
        float s = 0.f;
#pragma unroll
        for (int t = 0; t < 2; t++) {
            float4 v = p4[lane + t * 32];
            float x[4] = {v.x, v.y, v.z, v.w};
            uint32_t hb[4];
#pragma unroll
            for (int k = 0; k < 4; k++) {
                s += x[k] * x[k];
                col_acc[t * 4 + k] += x[k];
                hb[k] = (uint32_t)__half_as_ushort(__float2half_rn(x[k]));
            }
            size_t q = (size_t)row * 64 + lane + t * 32;   // uint2 index (4 halves)
            ((uint2*)g_h)[q] = make_uint2(hb[0] | (hb[1] << 16), hb[2] | (hb[3] << 16));
        }
#pragma unroll
        for (int o = 16; o > 0; o >>= 1) s += __shfl_xor_sync(0xffffffffu, s, o);
        if (lane == 0) { g_sq[row] = s; sq_acc += s; }
    }
    if (lane == 0) atomicAdd(&g_sumsq, (double)sq_acc);

#pragma unroll
    for (int t = 0; t < 2; t++)
#pragma unroll
        for (int k = 0; k < 4; k++)
            atomicAdd(&cs[t * 128 + lane * 4 + k], col_acc[t * 4 + k]);
    __syncthreads();
    atomicAdd(&g_colsum[tid], (double)cs[tid]);
}

__global__ void finalize_kernel() {
    __shared__ double red[DIM];
    int t = threadIdx.x;
    double c = g_colsum[t];
    red[t] = c * c;
    __syncthreads();
    for (int o = 128; o > 0; o >>= 1) {
        if (t < o) red[t] += red[t + o];
        __syncthreads();
    }
    if (t == 0) {
        double n = (double)NPTS;
        double sumL2 = 2.0 * n * g_sumsq - 2.0 * red[0];
        double bw = sumL2 / (n * n - n) / 4.0;   // / KERNEL_MUL^(KERNEL_NUM//2)
        g_c = (float)(-1.0 / (16.0 * bw * 0.6931471805599453));
    }
}

// ---------------------------------------------------------------- main tile kernel
// 256 threads, 8 warps (2x4), warp tile 64x32, CTA tile 128x128; 2 CTAs/SM.
// smem arrays per stage: A_h, B_h; each 128 rows x 80B (32 fp16 + pad)
#define STRIDE_B    80
#define ARR_BYTES   (128 * STRIDE_B)        // 10240
#define STAGE_BYTES (2 * ARR_BYTES)         // 20480
#define NSTAGE      4
#define DYN_SMEM    (NSTAGE * STAGE_BYTES)  // 81920

__global__ void __launch_bounds__(256, 2)
mmd_mma_kernel() {
    extern __shared__ char dsmem[];
    __shared__ float red[256];
    __shared__ float sqa_s[TILE];
    __shared__ float sqb_s[TILE];

    uint32_t dyn_u = smem_u32(dsmem);
    int tid  = threadIdx.x;
    int wid  = tid >> 5;
    int lane = tid & 31;
    int wm   = wid & 1;       // 2 warp-rows of 64
    int wn   = wid >> 1;      // 4 warp-cols of 32

    // decode linear block id -> (bi, bj), bi <= bj
    int b = blockIdx.x;
    float fb = (float)b;
    int bi = (int)((2.0f * NT + 1.0f - sqrtf((2.0f * NT + 1.0f) * (2.0f * NT + 1.0f) - 8.0f * fb)) * 0.5f);
    if (bi < 0) bi = 0;
    if (bi >= NT) bi = NT - 1;
#define TRI_START(i) ((i) * NT - (i) * ((i) - 1) / 2)
    while (bi + 1 < NT && TRI_START(bi + 1) <= b) bi++;
    while (bi > 0 && TRI_START(bi) > b) bi--;
    int bj = bi + (b - TRI_START(bi));
#undef TRI_START
    int row0 = bi * TILE;
    int col0 = bj * TILE;

    if (tid < TILE) {
        sqa_s[tid] = g_sq[row0 + tid];
        sqb_s[tid] = g_sq[col0 + tid];
    }

    const char* gbase[2];
    gbase[0] = (const char*)(g_h + (size_t)row0 * DIM);   // A
    gbase[1] = (const char*)(g_h + (size_t)col0 * DIM);   // B

    float acc[4][4][4];
#pragma unroll
    for (int mi = 0; mi < 4; mi++)
#pragma unroll
        for (int ni = 0; ni < 4; ni++)
#pragma unroll
            for (int e = 0; e < 4; e++) acc[mi][ni][e] = 0.f;

    // loader: 1024 x 16B per chunk; 256 threads -> 4 each
#define ISSUE_LOADS(c, s) do { \
    _Pragma("unroll") \
    for (int i = 0; i < 4; i++) { \
        int arr = i >> 1; \
        int rem = tid + (i & 1) * 256;      /* 0..511 */ \
        int row = rem >> 2; \
        int q   = rem & 3; \
        const char* srcp = gbase[arr] + (size_t)row * 512 + (c) * 64 + q * 16; \
        uint32_t dst = dyn_u + (s) * STAGE_BYTES + arr * ARR_BYTES + row * STRIDE_B + q * 16; \
        CP_ASYNC16(dst, srcp); \
    } \
    CP_COMMIT(); \
} while (0)

    // ldmatrix lane-address components
    int a_m    = lane >> 3;
    int a_rofs = ((a_m & 1) << 3) + (lane & 7);
    int a_koff = (a_m >> 1) << 4;
    int b_nofs = ((a_m >> 1) << 3) + (lane & 7);
    int b_koff = (a_m & 1) << 4;

    ISSUE_LOADS(0, 0);
    ISSUE_LOADS(1, 1);
    ISSUE_LOADS(2, 2);

    for (int c = 0; c < 8; c++) {
        int s = c & (NSTAGE - 1);
        CP_WAIT2();           // chunk c resident (at most c+1, c+2 pending)
        __syncthreads();      // all warps past chunk c-1 compute; stage (c+3)%4 free
        if (c + 3 < 8) ISSUE_LOADS(c + 3, (c + 3) & (NSTAGE - 1));

        uint32_t stage_u = dyn_u + s * STAGE_BYTES;
#pragma unroll
        for (int ks = 0; ks < 2; ks++) {
            uint32_t Ah[4][4], Bh[2][4];
#pragma unroll
            for (int mi = 0; mi < 4; mi++) {
                int r = wm * 64 + mi * 16 + a_rofs;
                uint32_t ad = stage_u + r * STRIDE_B + ks * 32 + a_koff;
                LDSM_X4(Ah[mi][0], Ah[mi][1], Ah[mi][2], Ah[mi][3], ad);
            }
#pragma unroll
            for (int pi = 0; pi < 2; pi++) {
                int nl = wn * 32 + pi * 16 + b_nofs;
                uint32_t bd = stage_u + ARR_BYTES + nl * STRIDE_B + ks * 32 + b_koff;
                LDSM_X4(Bh[pi][0], Bh[pi][1], Bh[pi][2], Bh[pi][3], bd);
            }
#pragma unroll
            for (int mi = 0; mi < 4; mi++) {
#pragma unroll
                for (int ni = 0; ni < 4; ni++) {
                    int pi = ni >> 1, h = (ni & 1) * 2;
                    MMA_F16(acc[mi][ni], Ah[mi], Bh[pi][h], Bh[pi][h + 1]);
                }
            }
        }
        // no trailing sync: next chunk's top barrier orders reads before refill
    }

    // epilogue: row = wm*64+mi*16 + lane/4 + (e>=2)*8 ; col = wn*32+ni*8 + (lane%4)*2 + (e&1)
    float cexp = g_c;
    int rlo = lane >> 2;
    int cl0 = (lane & 3) * 2;
    float s = 0.f;
#pragma unroll
    for (int mi = 0; mi < 4; mi++) {
        float sqr0 = sqa_s[wm * 64 + mi * 16 + rlo];
        float sqr1 = sqa_s[wm * 64 + mi * 16 + rlo + 8];
#pragma unroll
        for (int ni = 0; ni < 4; ni++) {
            float sqc0 = sqb_s[wn * 32 + ni * 8 + cl0];
            float sqc1 = sqb_s[wn * 32 + ni * 8 + cl0 + 1];
#pragma unroll
            for (int e = 0; e < 4; e++) {
                float sr = (e >= 2) ? sqr1 : sqr0;
                float sc = (e & 1) ? sqc1 : sqc0;
                float L2 = fmaxf(sr + sc - 2.f * acc[mi][ni][e], 0.f);
                float u;
                asm("ex2.approx.ftz.f32 %0, %1;" : "=f"(u) : "f"(L2 * cexp));
                float u2 = u * u, u4 = u2 * u2, u8 = u4 * u4;
                s += u + u2 + u4 + u8 + u8 * u8;
            }
        }
    }

    __syncthreads();
    red[tid] = s;
    __syncthreads();
#pragma unroll
    for (int o = 128; o > 0; o >>= 1) {
        if (tid < o) red[tid] += red[tid + o];
        __syncthreads();
    }
    if (tid == 0) {
        float w  = (bi == bj) ? 1.f : 2.f;
        float sr = (row0 < NSRC) ? 1.f : -1.f;
        float sc = (col0 < NSRC) ? 1.f : -1.f;
        atomicAdd(&g_acc, (double)(red[0] * w * sr * sc));
    }
}

__global__ void writeout_kernel(float* out) {
    out[0] = (float)(g_acc / ((double)NSRC * (double)NSRC));
}

// ---------------------------------------------------------------- launch
extern "C" void kernel_launch(void* const* d_in, const int* in_sizes, int n_in,
                              void* d_out, int out_size) {
    const float* src = (const float*)d_in[0];
    const float* tgt = (const float*)d_in[1];
    float* out = (float*)d_out;

    cudaFuncSetAttribute(mmd_mma_kernel, cudaFuncAttributeMaxDynamicSharedMemorySize, DYN_SMEM);

    zero_kernel<<<1, 256>>>();
    prep_kernel<<<NPTS / 64, 256>>>(src, tgt);     // fp16 convert + norms + colsums fused
    finalize_kernel<<<1, 256>>>();
    mmd_mma_kernel<<<NBLK, 256, DYN_SMEM>>>();
    writeout_kernel<<<1, 1>>>(out);
}

// round 10
// speedup vs baseline: 1.6987x; 1.1449x over previous
#include <cuda_runtime.h>
#include <cuda_fp16.h>
#include <math.h>
#include <stdint.h>

#define NPTS 8192
#define NSRC 4096
#define DIM  256
#define TILE 128
#define NT   (NPTS / TILE)          // 64
#define NBLK (NT * (NT + 1) / 2)    // 2080 upper-triangle tile pairs

// ---------------------------------------------------------------- scratch
__device__ float  g_sq[NPTS];
__device__ double g_colsum[DIM];
__device__ double g_sumsq;
__device__ float  g_c;              // exp2 scale: -1/(16*bw'*ln2)
__device__ double g_acc;
__device__ __half g_h[NPTS * DIM];

// ---------------------------------------------------------------- helpers
__device__ __forceinline__ uint32_t smem_u32(const void* p) {
    uint32_t a;
    asm("{ .reg .u64 t; cvta.to.shared.u64 t, %1; cvt.u32.u64 %0, t; }" : "=r"(a) : "l"(p));
    return a;
}
#define CP_ASYNC16(dst, src) \
    asm volatile("cp.async.cg.shared.global [%0], [%1], 16;" :: "r"(dst), "l"(src))
#define CP_COMMIT() asm volatile("cp.async.commit_group;" ::: "memory")
#define CP_WAIT1()  asm volatile("cp.async.wait_group 1;" ::: "memory")

#define LDSM_X4(r0, r1, r2, r3, a) \
    asm volatile("ldmatrix.sync.aligned.m8n8.x4.shared.b16 {%0,%1,%2,%3}, [%4];" \
        : "=r"(r0), "=r"(r1), "=r"(r2), "=r"(r3) : "r"(a))

#define MMA_F16(d, a, b0, b1) \
    asm volatile("mma.sync.aligned.m16n8k16.row.col.f32.f16.f16.f32 " \
        "{%0,%1,%2,%3}, {%4,%5,%6,%7}, {%8,%9}, {%0,%1,%2,%3};" \
        : "+f"((d)[0]), "+f"((d)[1]), "+f"((d)[2]), "+f"((d)[3]) \
        : "r"((a)[0]), "r"((a)[1]), "r"((a)[2]), "r"((a)[3]), "r"(b0), "r"(b1))

__device__ __forceinline__ const float* row_ptr(const float* src, const float* tgt, int i) {
    return (i < NSRC) ? (src + (size_t)i * DIM) : (tgt + (size_t)(i - NSRC) * DIM);
}

// ---------------------------------------------------------------- prep kernels
__global__ void zero_kernel() {
    int t = threadIdx.x;
    if (t < DIM) g_colsum[t] = 0.0;
    if (t == 0) { g_sumsq = 0.0; g_acc = 0.0; }
}

// 128 blocks x 256 threads; block handles 64 rows (warp -> 8 rows).
// Fused: fp16 convert + per-row ||x||^2 + column sums.
__global__ void prep_kernel(const float* __restrict__ src, const float* __restrict__ tgt) {
    __shared__ float cs[DIM];
    int tid  = threadIdx.x;
    int wid  = tid >> 5;
    int lane = tid & 31;
    cs[tid] = 0.f;
    __syncthreads();

    float col_acc[8] = {0, 0, 0, 0, 0, 0, 0, 0};
    float sq_acc = 0.f;

    int rbase = blockIdx.x * 64 + wid * 8;
    for (int rr = 0; rr < 8; rr++) {
        int row = rbase + rr;
        const float4* p4 = (const float4*)row_ptr(src, tgt, row);
        float s = 0.f;
#pragma unroll
        for (int t = 0; t < 2; t++) {
            float4 v = p4[lane + t * 32];
            float x[4] = {v.x, v.y, v.z, v.w};
            uint32_t hb[4];
#pragma unroll
            for (int k = 0; k < 4; k++) {
                s += x[k] * x[k];
                col_acc[t * 4 + k] += x[k];
                hb[k] = (uint32_t)__half_as_ushort(__float2half_rn(x[k]));
            }
            size_t q = (size_t)row * 64 + lane + t * 32;   // uint2 index (4 halves)
            ((uint2*)g_h)[q] = make_uint2(hb[0] | (hb[1] << 16), hb[2] | (hb[3] << 16));
        }
#pragma unroll
        for (int o = 16; o > 0; o >>= 1) s += __shfl_xor_sync(0xffffffffu, s, o);
        if (lane == 0) { g_sq[row] = s; sq_acc += s; }
    }
    if (lane == 0) atomicAdd(&g_sumsq, (double)sq_acc);

#pragma unroll
    for (int t = 0; t < 2; t++)
#pragma unroll
        for (int k = 0; k < 4; k++)
            atomicAdd(&cs[t * 128 + lane * 4 + k], col_acc[t * 4 + k]);
    __syncthreads();
    atomicAdd(&g_colsum[tid], (double)cs[tid]);
}

__global__ void finalize_kernel() {
    __shared__ double red[DIM];
    int t = threadIdx.x;
    double c = g_colsum[t];
    red[t] = c * c;
    __syncthreads();
    for (int o = 128; o > 0; o >>= 1) {
        if (t < o) red[t] += red[t + o];
        __syncthreads();
    }
    if (t == 0) {
        double n = (double)NPTS;
        double sumL2 = 2.0 * n * g_sumsq - 2.0 * red[0];
        double bw = sumL2 / (n * n - n) / 4.0;   // / KERNEL_MUL^(KERNEL_NUM//2)
        g_c = (float)(-1.0 / (16.0 * bw * 0.6931471805599453));
    }
}

// ---------------------------------------------------------------- main tile kernel
// 256 threads, 8 warps (2x4), warp tile 64x32, CTA tile 128x128; 2 CTAs/SM.
// K chunk = 64: smem arrays per stage: A, B; each 128 rows x 144B (64 fp16 + 16 pad)
#define STRIDE_B    144
#define ARR_BYTES   (128 * STRIDE_B)        // 18432
#define STAGE_BYTES (2 * ARR_BYTES)         // 36864
#define NSTAGE      3
#define NCHUNK      4
#define DYN_SMEM    (NSTAGE * STAGE_BYTES)  // 110592

__global__ void __launch_bounds__(256, 2)
mmd_mma_kernel() {
    extern __shared__ char dsmem[];
    __shared__ float red[8];
    __shared__ float sqa_s[TILE];
    __shared__ float sqb_s[TILE];

    uint32_t dyn_u = smem_u32(dsmem);
    int tid  = threadIdx.x;
    int wid  = tid >> 5;
    int lane = tid & 31;
    int wm   = wid & 1;       // 2 warp-rows of 64
    int wn   = wid >> 1;      // 4 warp-cols of 32

    // decode linear block id -> (bi, bj), bi <= bj
    int b = blockIdx.x;
    float fb = (float)b;
    int bi = (int)((2.0f * NT + 1.0f - sqrtf((2.0f * NT + 1.0f) * (2.0f * NT + 1.0f) - 8.0f * fb)) * 0.5f);
    if (bi < 0) bi = 0;
    if (bi >= NT) bi = NT - 1;
#define TRI_START(i) ((i) * NT - (i) * ((i) - 1) / 2)
    while (bi + 1 < NT && TRI_START(bi + 1) <= b) bi++;
    while (bi > 0 && TRI_START(bi) > b) bi--;
    int bj = bi + (b - TRI_START(bi));
#undef TRI_START
    int row0 = bi * TILE;
    int col0 = bj * TILE;

    if (tid < TILE) {
        sqa_s[tid] = g_sq[row0 + tid];
        sqb_s[tid] = g_sq[col0 + tid];
    }

    const char* gbase[2];
    gbase[0] = (const char*)(g_h + (size_t)row0 * DIM);   // A
    gbase[1] = (const char*)(g_h + (size_t)col0 * DIM);   // B

    float acc[4][4][4];
#pragma unroll
    for (int mi = 0; mi < 4; mi++)
#pragma unroll
        for (int ni = 0; ni < 4; ni++)
#pragma unroll
            for (int e = 0; e < 4; e++) acc[mi][ni][e] = 0.f;

    // loader: chunk c = k bytes [c*128, c*128+128); 2048 x 16B; 256 threads -> 8 each
#define ISSUE_LOADS(c, s) do { \
    _Pragma("unroll") \
    for (int i = 0; i < 8; i++) { \
        int arr = i >> 2; \
        int rem = tid + (i & 3) * 256;      /* 0..1023 */ \
        int row = rem >> 3; \
        int q   = rem & 7; \
        const char* srcp = gbase[arr] + (size_t)row * 512 + (c) * 128 + q * 16; \
        uint32_t dst = dyn_u + (s) * STAGE_BYTES + arr * ARR_BYTES + row * STRIDE_B + q * 16; \
        CP_ASYNC16(dst, srcp); \
    } \
    CP_COMMIT(); \
} while (0)

    // ldmatrix lane-address components
    int a_m    = lane >> 3;
    int a_rofs = ((a_m & 1) << 3) + (lane & 7);
    int a_koff = (a_m >> 1) << 4;
    int b_nofs = ((a_m >> 1) << 3) + (lane & 7);
    int b_koff = (a_m & 1) << 4;

    ISSUE_LOADS(0, 0);
    ISSUE_LOADS(1, 1);

    for (int c = 0; c < NCHUNK; c++) {
        CP_WAIT1();           // chunk c resident (exact accounting: empty groups committed below)
        __syncthreads();      // all warps past chunk c-1 compute; stage (c+2)%3 free
        if (c + 2 < NCHUNK) ISSUE_LOADS(c + 2, (c + 2) % NSTAGE);
        else CP_COMMIT();     // empty group keeps wait_group accounting exact

        uint32_t stage_u = dyn_u + (c % NSTAGE) * STAGE_BYTES;
#pragma unroll
        for (int ks = 0; ks < 4; ks++) {
            uint32_t Ah[4][4], Bh[2][4];
#pragma unroll
            for (int mi = 0; mi < 4; mi++) {
                int r = wm * 64 + mi * 16 + a_rofs;
                uint32_t ad = stage_u + r * STRIDE_B + ks * 32 + a_koff;
                LDSM_X4(Ah[mi][0], Ah[mi][1], Ah[mi][2], Ah[mi][3], ad);
            }
#pragma unroll
            for (int pi = 0; pi < 2; pi++) {
                int nl = wn * 32 + pi * 16 + b_nofs;
                uint32_t bd = stage_u + ARR_BYTES + nl * STRIDE_B + ks * 32 + b_koff;
                LDSM_X4(Bh[pi][0], Bh[pi][1], Bh[pi][2], Bh[pi][3], bd);
            }
#pragma unroll
            for (int mi = 0; mi < 4; mi++) {
#pragma unroll
                for (int ni = 0; ni < 4; ni++) {
                    int pi = ni >> 1, h = (ni & 1) * 2;
                    MMA_F16(acc[mi][ni], Ah[mi], Bh[pi][h], Bh[pi][h + 1]);
                }
            }
        }
        // no trailing sync: next chunk's top barrier orders reads before refill
    }

    // epilogue: row = wm*64+mi*16 + lane/4 + (e>=2)*8 ; col = wn*32+ni*8 + (lane%4)*2 + (e&1)
    float cexp = g_c;
    int rlo = lane >> 2;
    int cl0 = (lane & 3) * 2;
    float s = 0.f;
#pragma unroll
    for (int mi = 0; mi < 4; mi++) {
        float sqr0 = sqa_s[wm * 64 + mi * 16 + rlo];
        float sqr1 = sqa_s[wm * 64 + mi * 16 + rlo + 8];
#pragma unroll
        for (int ni = 0; ni < 4; ni++) {
            float sqc0 = sqb_s[wn * 32 + ni * 8 + cl0];
            float sqc1 = sqb_s[wn * 32 + ni * 8 + cl0 + 1];
#pragma unroll
            for (int e = 0; e < 4; e++) {
                float sr = (e >= 2) ? sqr1 : sqr0;
                float sc = (e & 1) ? sqc1 : sqc0;
                float L2 = fmaxf(sr + sc - 2.f * acc[mi][ni][e], 0.f);
                float u;
                asm("ex2.approx.ftz.f32 %0, %1;" : "=f"(u) : "f"(L2 * cexp));
                float u2 = u * u, u4 = u2 * u2, u8 = u4 * u4;
                s += u + u2 + u4 + u8 + u8 * u8;
            }
        }
    }

    // warp-shuffle reduce, then tiny cross-warp fold
#pragma unroll
    for (int o = 16; o > 0; o >>= 1) s += __shfl_xor_sync(0xffffffffu, s, o);
    if (lane == 0) red[wid] = s;
    __syncthreads();
    if (tid == 0) {
        float t = 0.f;
#pragma unroll
        for (int i = 0; i < 8; i++) t += red[i];
        float w  = (bi == bj) ? 1.f : 2.f;
        float sr = (row0 < NSRC) ? 1.f : -1.f;
        float sc = (col0 < NSRC) ? 1.f : -1.f;
        atomicAdd(&g_acc, (double)(t * w * sr * sc));
    }
}

__global__ void writeout_kernel(float* out) {
    out[0] = (float)(g_acc / ((double)NSRC * (double)NSRC));
}

// ---------------------------------------------------------------- launch
extern "C" void kernel_launch(void* const* d_in, const int* in_sizes, int n_in,
                              void* d_out, int out_size) {
    const float* src = (const float*)d_in[0];
    const float* tgt = (const float*)d_in[1];
    float* out = (float*)d_out;

    cudaFuncSetAttribute(mmd_mma_kernel, cudaFuncAttributeMaxDynamicSharedMemorySize, DYN_SMEM);

    zero_kernel<<<1, 256>>>();
    prep_kernel<<<NPTS / 64, 256>>>(src, tgt);     // fp16 convert + norms + colsums fused
    finalize_kernel<<<1, 256>>>();
    mmd_mma_kernel<<<NBLK, 256, DYN_SMEM>>>();
    writeout_kernel<<<1, 1>>>(out);
}

// round 11
// speedup vs baseline: 1.7104x; 1.0069x over previous
#include <cuda_runtime.h>
#include <cuda_fp16.h>
#include <math.h>
#include <stdint.h>

#define NPTS 8192
#define NSRC 4096
#define DIM  256
#define TILE 128
#define NT   (NPTS / TILE)          // 64
#define NBLK (NT * (NT + 1) / 2)    // 2080 upper-triangle tile pairs

// ---------------------------------------------------------------- scratch
__device__ float  g_sq[NPTS];
__device__ double g_colsum[DIM];
__device__ double g_sumsq;
__device__ float  g_c;              // exp2 scale: -1/(16*bw'*ln2)
__device__ double g_acc;
__device__ __half g_h[NPTS * DIM];

// ---------------------------------------------------------------- helpers
__device__ __forceinline__ uint32_t smem_u32(const void* p) {
    uint32_t a;
    asm("{ .reg .u64 t; cvta.to.shared.u64 t, %1; cvt.u32.u64 %0, t; }" : "=r"(a) : "l"(p));
    return a;
}
#define CP_ASYNC16(dst, src) \
    asm volatile("cp.async.cg.shared.global [%0], [%1], 16;" :: "r"(dst), "l"(src))
#define CP_COMMIT() asm volatile("cp.async.commit_group;" ::: "memory")
#define CP_WAIT1()  asm volatile("cp.async.wait_group 1;" ::: "memory")

#define LDSM_X4(r0, r1, r2, r3, a) \
    asm volatile("ldmatrix.sync.aligned.m8n8.x4.shared.b16 {%0,%1,%2,%3}, [%4];" \
        : "=r"(r0), "=r"(r1), "=r"(r2), "=r"(r3) : "r"(a))

// fp16-accumulator MMA: D,C packed 2 halves/reg
#define MMA_F16A(d, a, b0, b1) \
    asm volatile("mma.sync.aligned.m16n8k16.row.col.f16.f16.f16.f16 " \
        "{%0,%1}, {%2,%3,%4,%5}, {%6,%7}, {%0,%1};" \
        : "+r"((d)[0]), "+r"((d)[1]) \
        : "r"((a)[0]), "r"((a)[1]), "r"((a)[2]), "r"((a)[3]), "r"(b0), "r"(b1))

__device__ __forceinline__ const float* row_ptr(const float* src, const float* tgt, int i) {
    return (i < NSRC) ? (src + (size_t)i * DIM) : (tgt + (size_t)(i - NSRC) * DIM);
}

// ---------------------------------------------------------------- prep kernels
__global__ void zero_kernel() {
    int t = threadIdx.x;
    if (t < DIM) g_colsum[t] = 0.0;
    if (t == 0) { g_sumsq = 0.0; g_acc = 0.0; }
}

// 128 blocks x 256 threads; block handles 64 rows (warp -> 8 rows).
// Fused: fp16 convert + per-row ||x||^2 + column sums.
__global__ void prep_kernel(const float* __restrict__ src, const float* __restrict__ tgt) {
    __shared__ float cs[DIM];
    int tid  = threadIdx.x;
    int wid  = tid >> 5;
    int lane = tid & 31;
    cs[tid] = 0.f;
    __syncthreads();

    float col_acc[8] = {0, 0, 0, 0, 0, 0, 0, 0};
    float sq_acc = 0.f;

    int rbase = blockIdx.x * 64 + wid * 8;
    for (int rr = 0; rr < 8; rr++) {
        int row = rbase + rr;
        const float4* p4 = (const float4*)row_ptr(src, tgt, row);
        float s = 0.f;
#pragma unroll
        for (int t = 0; t < 2; t++) {
            float4 v = p4[lane + t * 32];
            float x[4] = {v.x, v.y, v.z, v.w};
            uint32_t hb[4];
#pragma unroll
            for (int k = 0; k < 4; k++) {
                s += x[k] * x[k];
                col_acc[t * 4 + k] += x[k];
                hb[k] = (uint32_t)__half_as_ushort(__float2half_rn(x[k]));
            }
            size_t q = (size_t)row * 64 + lane + t * 32;   // uint2 index (4 halves)
            ((uint2*)g_h)[q] = make_uint2(hb[0] | (hb[1] << 16), hb[2] | (hb[3] << 16));
        }
#pragma unroll
        for (int o = 16; o > 0; o >>= 1) s += __shfl_xor_sync(0xffffffffu, s, o);
        if (lane == 0) { g_sq[row] = s; sq_acc += s; }
    }
    if (lane == 0) atomicAdd(&g_sumsq, (double)sq_acc);

#pragma unroll
    for (int t = 0; t < 2; t++)
#pragma unroll
        for (int k = 0; k < 4; k++)
            atomicAdd(&cs[t * 128 + lane * 4 + k], col_acc[t * 4 + k]);
    __syncthreads();
    atomicAdd(&g_colsum[tid], (double)cs[tid]);
}

__global__ void finalize_kernel() {
    __shared__ double red[DIM];
    int t = threadIdx.x;
    double c = g_colsum[t];
    red[t] = c * c;
    __syncthreads();
    for (int o = 128; o > 0; o >>= 1) {
        if (t < o) red[t] += red[t + o];
        __syncthreads();
    }
    if (t == 0) {
        double n = (double)NPTS;
        double sumL2 = 2.0 * n * g_sumsq - 2.0 * red[0];
        double bw = sumL2 / (n * n - n) / 4.0;   // / KERNEL_MUL^(KERNEL_NUM//2)
        g_c = (float)(-1.0 / (16.0 * bw * 0.6931471805599453));
    }
}

// ---------------------------------------------------------------- main tile kernel
// 256 threads, 8 warps (2x4), warp tile 64x32, CTA tile 128x128; 2 CTAs/SM.
// K chunk = 64: smem arrays per stage: A, B; each 128 rows x 144B (64 fp16 + 16 pad)
#define STRIDE_B    144
#define ARR_BYTES   (128 * STRIDE_B)        // 18432
#define STAGE_BYTES (2 * ARR_BYTES)         // 36864
#define NSTAGE      3
#define NCHUNK      4
#define DYN_SMEM    (NSTAGE * STAGE_BYTES)  // 110592

__global__ void __launch_bounds__(256, 2)
mmd_mma_kernel() {
    extern __shared__ char dsmem[];
    __shared__ float red[8];
    __shared__ float sqa_s[TILE];
    __shared__ float sqb_s[TILE];

    uint32_t dyn_u = smem_u32(dsmem);
    int tid  = threadIdx.x;
    int wid  = tid >> 5;
    int lane = tid & 31;
    int wm   = wid & 1;       // 2 warp-rows of 64
    int wn   = wid >> 1;      // 4 warp-cols of 32

    // decode linear block id -> (bi, bj), bi <= bj
    int b = blockIdx.x;
    float fb = (float)b;
    int bi = (int)((2.0f * NT + 1.0f - sqrtf((2.0f * NT + 1.0f) * (2.0f * NT + 1.0f) - 8.0f * fb)) * 0.5f);
    if (bi < 0) bi = 0;
    if (bi >= NT) bi = NT - 1;
#define TRI_START(i) ((i) * NT - (i) * ((i) - 1) / 2)
    while (bi + 1 < NT && TRI_START(bi + 1) <= b) bi++;
    while (bi > 0 && TRI_START(bi) > b) bi--;
    int bj = bi + (b - TRI_START(bi));
#undef TRI_START
    int row0 = bi * TILE;
    int col0 = bj * TILE;

    if (tid < TILE) {
        sqa_s[tid] = g_sq[row0 + tid];
        sqb_s[tid] = g_sq[col0 + tid];
    }

    const char* gbase[2];
    gbase[0] = (const char*)(g_h + (size_t)row0 * DIM);   // A
    gbase[1] = (const char*)(g_h + (size_t)col0 * DIM);   // B

    uint32_t acc[4][4][2];    // fp16x2 accumulators
#pragma unroll
    for (int mi = 0; mi < 4; mi++)
#pragma unroll
        for (int ni = 0; ni < 4; ni++) {
            acc[mi][ni][0] = 0u;
            acc[mi][ni][1] = 0u;
        }

    // loader: chunk c = k bytes [c*128, c*128+128); 2048 x 16B; 256 threads -> 8 each
#define ISSUE_LOADS(c, s) do { \
    _Pragma("unroll") \
    for (int i = 0; i < 8; i++) { \
        int arr = i >> 2; \
        int rem = tid + (i & 3) * 256;      /* 0..1023 */ \
        int row = rem >> 3; \
        int q   = rem & 7; \
        const char* srcp = gbase[arr] + (size_t)row * 512 + (c) * 128 + q * 16; \
        uint32_t dst = dyn_u + (s) * STAGE_BYTES + arr * ARR_BYTES + row * STRIDE_B + q * 16; \
        CP_ASYNC16(dst, srcp); \
    } \
    CP_COMMIT(); \
} while (0)

    // ldmatrix lane-address components
    int a_m    = lane >> 3;
    int a_rofs = ((a_m & 1) << 3) + (lane & 7);
    int a_koff = (a_m >> 1) << 4;
    int b_nofs = ((a_m >> 1) << 3) + (lane & 7);
    int b_koff = (a_m & 1) << 4;

    // fragment loader (double-buffered)
#define LOAD_FRAGS(buf, stage_u, ks) do { \
    _Pragma("unroll") \
    for (int mi = 0; mi < 4; mi++) { \
        int r = wm * 64 + mi * 16 + a_rofs; \
        uint32_t ad = (stage_u) + r * STRIDE_B + (ks) * 32 + a_koff; \
        LDSM_X4(Af[buf][mi][0], Af[buf][mi][1], Af[buf][mi][2], Af[buf][mi][3], ad); \
    } \
    _Pragma("unroll") \
    for (int pi = 0; pi < 2; pi++) { \
        int nl = wn * 32 + pi * 16 + b_nofs; \
        uint32_t bd = (stage_u) + ARR_BYTES + nl * STRIDE_B + (ks) * 32 + b_koff; \
        LDSM_X4(Bf[buf][pi][0], Bf[buf][pi][1], Bf[buf][pi][2], Bf[buf][pi][3], bd); \
    } \
} while (0)

#define DO_MMAS(buf) do { \
    _Pragma("unroll") \
    for (int mi = 0; mi < 4; mi++) { \
        _Pragma("unroll") \
        for (int ni = 0; ni < 4; ni++) { \
            int pi = ni >> 1, h = (ni & 1) * 2; \
            MMA_F16A(acc[mi][ni], Af[buf][mi], Bf[buf][pi][h], Bf[buf][pi][h + 1]); \
        } \
    } \
} while (0)

    uint32_t Af[2][4][4], Bf[2][2][4];

    ISSUE_LOADS(0, 0);
    ISSUE_LOADS(1, 1);

    for (int c = 0; c < NCHUNK; c++) {
        CP_WAIT1();           // chunk c resident
        __syncthreads();      // all warps past chunk c-1 compute; stage (c+2)%3 free
        if (c + 2 < NCHUNK) ISSUE_LOADS(c + 2, (c + 2) % NSTAGE);
        else CP_COMMIT();     // empty group keeps wait_group accounting exact

        uint32_t stage_u = dyn_u + (c % NSTAGE) * STAGE_BYTES;
        LOAD_FRAGS(0, stage_u, 0);
#pragma unroll
        for (int ks = 0; ks < 4; ks++) {
            int cur = ks & 1;
            if (ks < 3) LOAD_FRAGS(cur ^ 1, stage_u, ks + 1);
            DO_MMAS(cur);
        }
        // no trailing sync: next chunk's top barrier orders reads before refill
    }

    // epilogue: row = wm*64+mi*16 + lane/4 + (e>=2)*8 ; col = wn*32+ni*8 + (lane%4)*2 + (e&1)
    float cexp = g_c;
    int rlo = lane >> 2;
    int cl0 = (lane & 3) * 2;
    float s = 0.f;
#pragma unroll
    for (int mi = 0; mi < 4; mi++) {
        float sqr0 = sqa_s[wm * 64 + mi * 16 + rlo];
        float sqr1 = sqa_s[wm * 64 + mi * 16 + rlo + 8];
#pragma unroll
        for (int ni = 0; ni < 4; ni++) {
            float sqc0 = sqb_s[wn * 32 + ni * 8 + cl0];
            float sqc1 = sqb_s[wn * 32 + ni * 8 + cl0 + 1];
            float2 p0 = __half22float2(*(__half2*)&acc[mi][ni][0]);  // e0, e1
            float2 p1 = __half22float2(*(__half2*)&acc[mi][ni][1]);  // e2, e3
            float dots[4] = {p0.x, p0.y, p1.x, p1.y};
#pragma unroll
            for (int e = 0; e < 4; e++) {
                float sr = (e >= 2) ? sqr1 : sqr0;
                float sc = (e & 1) ? sqc1 : sqc0;
                float L2 = fmaxf(sr + sc - 2.f * dots[e], 0.f);
                float u;
                asm("ex2.approx.ftz.f32 %0, %1;" : "=f"(u) : "f"(L2 * cexp));
                float u2 = u * u, u4 = u2 * u2, u8 = u4 * u4;
                s += u + u2 + u4 + u8 + u8 * u8;
            }
        }
    }

    // warp-shuffle reduce, then tiny cross-warp fold
#pragma unroll
    for (int o = 16; o > 0; o >>= 1) s += __shfl_xor_sync(0xffffffffu, s, o);
    if (lane == 0) red[wid] = s;
    __syncthreads();
    if (tid == 0) {
        float t = 0.f;
#pragma unroll
        for (int i = 0; i < 8; i++) t += red[i];
        float w  = (bi == bj) ? 1.f : 2.f;
        float sr = (row0 < NSRC) ? 1.f : -1.f;
        float sc = (col0 < NSRC) ? 1.f : -1.f;
        atomicAdd(&g_acc, (double)(t * w * sr * sc));
    }
}

__global__ void writeout_kernel(float* out) {
    out[0] = (float)(g_acc / ((double)NSRC * (double)NSRC));
}

// ---------------------------------------------------------------- launch
extern "C" void kernel_launch(void* const* d_in, const int* in_sizes, int n_in,
                              void* d_out, int out_size) {
    const float* src = (const float*)d_in[0];
    const float* tgt = (const float*)d_in[1];
    float* out = (float*)d_out;

    cudaFuncSetAttribute(mmd_mma_kernel, cudaFuncAttributeMaxDynamicSharedMemorySize, DYN_SMEM);

    zero_kernel<<<1, 256>>>();
    prep_kernel<<<NPTS / 64, 256>>>(src, tgt);     // fp16 convert + norms + colsums fused
    finalize_kernel<<<1, 256>>>();
    mmd_mma_kernel<<<NBLK, 256, DYN_SMEM>>>();
    writeout_kernel<<<1, 1>>>(out);
}

// round 12
// speedup vs baseline: 1.8057x; 1.0557x over previous
#include <cuda_runtime.h>
#include <cuda_fp16.h>
#include <math.h>
#include <stdint.h>

#define NPTS 8192
#define NSRC 4096
#define DIM  256
#define TILE 128
#define NT   (NPTS / TILE)          // 64
#define NBLK (NT * (NT + 1) / 2)    // 2080 upper-triangle tile pairs

// ---------------------------------------------------------------- scratch
__device__ float  g_sq[NPTS];
__device__ double g_colsum[DIM];
__device__ double g_sumsq;
__device__ float  g_c;              // exp2 scale: -1/(16*bw'*ln2)
__device__ double g_acc;
__device__ __half g_h[NPTS * DIM];

// ---------------------------------------------------------------- helpers
__device__ __forceinline__ uint32_t smem_u32(const void* p) {
    uint32_t a;
    asm("{ .reg .u64 t; cvta.to.shared.u64 t, %1; cvt.u32.u64 %0, t; }" : "=r"(a) : "l"(p));
    return a;
}
#define CP_ASYNC16(dst, src) \
    asm volatile("cp.async.cg.shared.global [%0], [%1], 16;" :: "r"(dst), "l"(src))
#define CP_COMMIT() asm volatile("cp.async.commit_group;" ::: "memory")
#define CP_WAIT1()  asm volatile("cp.async.wait_group 1;" ::: "memory")

#define LDSM_X4(r0, r1, r2, r3, a) \
    asm volatile("ldmatrix.sync.aligned.m8n8.x4.shared.b16 {%0,%1,%2,%3}, [%4];" \
        : "=r"(r0), "=r"(r1), "=r"(r2), "=r"(r3) : "r"(a))

// fp16-accumulator MMA: D,C packed 2 halves/reg
#define MMA_F16A(d, a, b0, b1) \
    asm volatile("mma.sync.aligned.m16n8k16.row.col.f16.f16.f16.f16 " \
        "{%0,%1}, {%2,%3,%4,%5}, {%6,%7}, {%0,%1};" \
        : "+r"((d)[0]), "+r"((d)[1]) \
        : "r"((a)[0]), "r"((a)[1]), "r"((a)[2]), "r"((a)[3]), "r"(b0), "r"(b1))

__device__ __forceinline__ const float* row_ptr(const float* src, const float* tgt, int i) {
    return (i < NSRC) ? (src + (size_t)i * DIM) : (tgt + (size_t)(i - NSRC) * DIM);
}

// ---------------------------------------------------------------- prep kernels
__global__ void zero_kernel() {
    int t = threadIdx.x;
    if (t < DIM) g_colsum[t] = 0.0;
    if (t == 0) { g_sumsq = 0.0; g_acc = 0.0; }
}

// 256 blocks x 256 threads; block handles 32 rows (warp -> 4 rows).
// Fused: fp16 convert + per-row ||x||^2 + column sums.
__global__ void prep_kernel(const float* __restrict__ src, const float* __restrict__ tgt) {
    __shared__ float cs[DIM];
    int tid  = threadIdx.x;
    int wid  = tid >> 5;
    int lane = tid & 31;
    cs[tid] = 0.f;
    __syncthreads();

    float col_acc[8] = {0, 0, 0, 0, 0, 0, 0, 0};
    float sq_acc = 0.f;

    int rbase = blockIdx.x * 32 + wid * 4;
    for (int rr = 0; rr < 4; rr++) {
        int row = rbase + rr;
        const float4* p4 = (const float4*)row_ptr(src, tgt, row);
        float s = 0.f;
#pragma unroll
        for (int t = 0; t < 2; t++) {
            float4 v = p4[lane + t * 32];
            float x[4] = {v.x, v.y, v.z, v.w};
            uint32_t hb[4];
#pragma unroll
            for (int k = 0; k < 4; k++) {
                s += x[k] * x[k];
                col_acc[t * 4 + k] += x[k];
                hb[k] = (uint32_t)__half_as_ushort(__float2half_rn(x[k]));
            }
            size_t q = (size_t)row * 64 + lane + t * 32;   // uint2 index (4 halves)
            ((uint2*)g_h)[q] = make_uint2(hb[0] | (hb[1] << 16), hb[2] | (hb[3] << 16));
        }
#pragma unroll
        for (int o = 16; o > 0; o >>= 1) s += __shfl_xor_sync(0xffffffffu, s, o);
        if (lane == 0) { g_sq[row] = s; sq_acc += s; }
    }
    if (lane == 0) atomicAdd(&g_sumsq, (double)sq_acc);

#pragma unroll
    for (int t = 0; t < 2; t++)
#pragma unroll
        for (int k = 0; k < 4; k++)
            atomicAdd(&cs[t * 128 + lane * 4 + k], col_acc[t * 4 + k]);
    __syncthreads();
    atomicAdd(&g_colsum[tid], (double)cs[tid]);
}

__global__ void finalize_kernel() {
    __shared__ double red[DIM];
    int t = threadIdx.x;
    double c = g_colsum[t];
    red[t] = c * c;
    __syncthreads();
    for (int o = 128; o > 0; o >>= 1) {
        if (t < o) red[t] += red[t + o];
        __syncthreads();
    }
    if (t == 0) {
        double n = (double)NPTS;
        double sumL2 = 2.0 * n * g_sumsq - 2.0 * red[0];
        double bw = sumL2 / (n * n - n) / 4.0;   // / KERNEL_MUL^(KERNEL_NUM//2)
        g_c = (float)(-1.0 / (16.0 * bw * 0.6931471805599453));
    }
}

// ---------------------------------------------------------------- main tile kernel
// 256 threads, 8 warps (2x4), warp tile 64x32, CTA tile 128x128; 2 CTAs/SM.
// K chunk = 64: smem arrays per stage: A, B; each 128 rows x 144B (64 fp16 + 16 pad)
#define STRIDE_B    144
#define ARR_BYTES   (128 * STRIDE_B)        // 18432
#define STAGE_BYTES (2 * ARR_BYTES)         // 36864
#define NSTAGE      3
#define NCHUNK      4
#define DYN_SMEM    (NSTAGE * STAGE_BYTES)  // 110592

__global__ void __launch_bounds__(256, 2)
mmd_mma_kernel() {
    extern __shared__ char dsmem[];
    __shared__ float red[8];
    __shared__ float sqa_s[TILE];
    __shared__ float sqb_s[TILE];

    uint32_t dyn_u = smem_u32(dsmem);
    int tid  = threadIdx.x;
    int wid  = tid >> 5;
    int lane = tid & 31;
    int wm   = wid & 1;       // 2 warp-rows of 64
    int wn   = wid >> 1;      // 4 warp-cols of 32

    // decode linear block id -> (bi, bj), bi <= bj
    int b = blockIdx.x;
    float fb = (float)b;
    int bi = (int)((2.0f * NT + 1.0f - sqrtf((2.0f * NT + 1.0f) * (2.0f * NT + 1.0f) - 8.0f * fb)) * 0.5f);
    if (bi < 0) bi = 0;
    if (bi >= NT) bi = NT - 1;
#define TRI_START(i) ((i) * NT - (i) * ((i) - 1) / 2)
    while (bi + 1 < NT && TRI_START(bi + 1) <= b) bi++;
    while (bi > 0 && TRI_START(bi) > b) bi--;
    int bj = bi + (b - TRI_START(bi));
#undef TRI_START
    int row0 = bi * TILE;
    int col0 = bj * TILE;

    if (tid < TILE) {
        sqa_s[tid] = g_sq[row0 + tid];
        sqb_s[tid] = g_sq[col0 + tid];
    }

    const char* gbase[2];
    gbase[0] = (const char*)(g_h + (size_t)row0 * DIM);   // A
    gbase[1] = (const char*)(g_h + (size_t)col0 * DIM);   // B

    uint32_t acc[4][4][2];    // fp16x2 accumulators
#pragma unroll
    for (int mi = 0; mi < 4; mi++)
#pragma unroll
        for (int ni = 0; ni < 4; ni++) {
            acc[mi][ni][0] = 0u;
            acc[mi][ni][1] = 0u;
        }

    // loader: chunk c = k bytes [c*128, c*128+128); 2048 x 16B; 256 threads -> 8 each
#define ISSUE_LOADS(c, s) do { \
    _Pragma("unroll") \
    for (int i = 0; i < 8; i++) { \
        int arr = i >> 2; \
        int rem = tid + (i & 3) * 256;      /* 0..1023 */ \
        int row = rem >> 3; \
        int q   = rem & 7; \
        const char* srcp = gbase[arr] + (size_t)row * 512 + (c) * 128 + q * 16; \
        uint32_t dst = dyn_u + (s) * STAGE_BYTES + arr * ARR_BYTES + row * STRIDE_B + q * 16; \
        CP_ASYNC16(dst, srcp); \
    } \
    CP_COMMIT(); \
} while (0)

    // ldmatrix lane-address components
    int a_m    = lane >> 3;
    int a_rofs = ((a_m & 1) << 3) + (lane & 7);
    int a_koff = (a_m >> 1) << 4;
    int b_nofs = ((a_m >> 1) << 3) + (lane & 7);
    int b_koff = (a_m & 1) << 4;

    // fragment loader (double-buffered)
#define LOAD_FRAGS(buf, stage_u, ks) do { \
    _Pragma("unroll") \
    for (int mi = 0; mi < 4; mi++) { \
        int r = wm * 64 + mi * 16 + a_rofs; \
        uint32_t ad = (stage_u) + r * STRIDE_B + (ks) * 32 + a_koff; \
        LDSM_X4(Af[buf][mi][0], Af[buf][mi][1], Af[buf][mi][2], Af[buf][mi][3], ad); \
    } \
    _Pragma("unroll") \
    for (int pi = 0; pi < 2; pi++) { \
        int nl = wn * 32 + pi * 16 + b_nofs; \
        uint32_t bd = (stage_u) + ARR_BYTES + nl * STRIDE_B + (ks) * 32 + b_koff; \
        LDSM_X4(Bf[buf][pi][0], Bf[buf][pi][1], Bf[buf][pi][2], Bf[buf][pi][3], bd); \
    } \
} while (0)

#define DO_MMAS(buf) do { \
    _Pragma("unroll") \
    for (int mi = 0; mi < 4; mi++) { \
        _Pragma("unroll") \
        for (int ni = 0; ni < 4; ni++) { \
            int pi = ni >> 1, h = (ni & 1) * 2; \
            MMA_F16A(acc[mi][ni], Af[buf][mi], Bf[buf][pi][h], Bf[buf][pi][h + 1]); \
        } \
    } \
} while (0)

    uint32_t Af[2][4][4], Bf[2][2][4];

    ISSUE_LOADS(0, 0);
    ISSUE_LOADS(1, 1);

    for (int c = 0; c < NCHUNK; c++) {
        CP_WAIT1();           // chunk c resident
        __syncthreads();      // all warps past chunk c-1 compute; stage (c+2)%3 free
        if (c + 2 < NCHUNK) ISSUE_LOADS(c + 2, (c + 2) % NSTAGE);
        else CP_COMMIT();     // empty group keeps wait_group accounting exact

        uint32_t stage_u = dyn_u + (c % NSTAGE) * STAGE_BYTES;
        LOAD_FRAGS(0, stage_u, 0);
#pragma unroll
        for (int ks = 0; ks < 4; ks++) {
            int cur = ks & 1;
            if (ks < 3) LOAD_FRAGS(cur ^ 1, stage_u, ks + 1);
            DO_MMAS(cur);
        }
        // no trailing sync: next chunk's top barrier orders reads before refill
    }

    // ---------------- epilogue (fp16x2 vectorized) ----------------
    // element map: row = wm*64+mi*16 + lane/4 + (p)*8 ; col = wn*32+ni*8 + (lane%4)*2 + {0,1}
    float cexp = g_c;
    float m2c  = -2.f * cexp;
    int rlo = lane >> 2;
    int cl0 = (lane & 3) * 2;

    float tB0[4], tB1[4];
#pragma unroll
    for (int ni = 0; ni < 4; ni++) {
        tB0[ni] = cexp * sqb_s[wn * 32 + ni * 8 + cl0];
        tB1[ni] = cexp * sqb_s[wn * 32 + ni * 8 + cl0 + 1];
    }

    float s = 0.f;
#pragma unroll
    for (int mi = 0; mi < 4; mi++) {
        float tA[2];
        tA[0] = cexp * sqa_s[wm * 64 + mi * 16 + rlo];
        tA[1] = cexp * sqa_s[wm * 64 + mi * 16 + rlo + 8];
        __half2 s2 = __float2half2_rn(0.f);
#pragma unroll
        for (int ni = 0; ni < 4; ni++) {
#pragma unroll
            for (int p = 0; p < 2; p++) {
                float2 d = __half22float2(*(__half2*)&acc[mi][ni][p]);
                float t0 = fmaf(d.x, m2c, tA[p] + tB0[ni]);
                float t1 = fmaf(d.y, m2c, tA[p] + tB1[ni]);
                __half2 t2 = __floats2half2_rn(t0, t1);
                __half2 u  = h2exp2(t2);
                __half2 u2  = __hmul2(u, u);
                __half2 u4  = __hmul2(u2, u2);
                __half2 u8  = __hmul2(u4, u4);
                __half2 u16 = __hmul2(u8, u8);
                __half2 sm = __hadd2(__hadd2(__hadd2(u, u2), __hadd2(u4, u8)), u16);
                s2 = __hadd2(s2, sm);
            }
        }
        float2 f = __half22float2(s2);
        s += f.x + f.y;
    }

    // warp-shuffle reduce, then tiny cross-warp fold
#pragma unroll
    for (int o = 16; o > 0; o >>= 1) s += __shfl_xor_sync(0xffffffffu, s, o);
    if (lane == 0) red[wid] = s;
    __syncthreads();
    if (tid == 0) {
        float t = 0.f;
#pragma unroll
        for (int i = 0; i < 8; i++) t += red[i];
        float w  = (bi == bj) ? 1.f : 2.f;
        float sr = (row0 < NSRC) ? 1.f : -1.f;
        float sc = (col0 < NSRC) ? 1.f : -1.f;
        atomicAdd(&g_acc, (double)(t * w * sr * sc));
    }
}

__global__ void writeout_kernel(float* out) {
    out[0] = (float)(g_acc / ((double)NSRC * (double)NSRC));
}

// ---------------------------------------------------------------- launch
extern "C" void kernel_launch(void* const* d_in, const int* in_sizes, int n_in,
                              void* d_out, int out_size) {
    const float* src = (const float*)d_in[0];
    const float* tgt = (const float*)d_in[1];
    float* out = (float*)d_out;

    cudaFuncSetAttribute(mmd_mma_kernel, cudaFuncAttributeMaxDynamicSharedMemorySize, DYN_SMEM);

    zero_kernel<<<1, 256>>>();
    prep_kernel<<<NPTS / 32, 256>>>(src, tgt);     // fp16 convert + norms + colsums fused
    finalize_kernel<<<1, 256>>>();
    mmd_mma_kernel<<<NBLK, 256, DYN_SMEM>>>();
    writeout_kernel<<<1, 1>>>(out);
}

// round 13
// speedup vs baseline: 1.8682x; 1.0346x over previous
#include <cuda_runtime.h>
#include <cuda_fp16.h>
#include <math.h>
#include <stdint.h>

#define NPTS 8192
#define NSRC 4096
#define DIM  256
#define TILE 128
#define NT   (NPTS / TILE)          // 64
#define NBLK (NT * (NT + 1) / 2)    // 2080 upper-triangle tile pairs

// ---------------------------------------------------------------- scratch
// NOTE: device globals are zero-initialized at module load; writeout_kernel
// re-zeros the accumulators at the end of every launch so graph replays see
// the same initial state.
__device__ float  g_sq[NPTS];
__device__ double g_colsum[DIM];
__device__ double g_sumsq;
__device__ float  g_c;              // exp2 scale: -1/(16*bw'*ln2)
__device__ double g_acc;
__device__ __half g_h[NPTS * DIM];

// ---------------------------------------------------------------- helpers
__device__ __forceinline__ uint32_t smem_u32(const void* p) {
    uint32_t a;
    asm("{ .reg .u64 t; cvta.to.shared.u64 t, %1; cvt.u32.u64 %0, t; }" : "=r"(a) : "l"(p));
    return a;
}
#define CP_ASYNC16(dst, src) \
    asm volatile("cp.async.cg.shared.global [%0], [%1], 16;" :: "r"(dst), "l"(src))
#define CP_COMMIT() asm volatile("cp.async.commit_group;" ::: "memory")
#define CP_WAIT1()  asm volatile("cp.async.wait_group 1;" ::: "memory")

#define LDSM_X4(r0, r1, r2, r3, a) \
    asm volatile("ldmatrix.sync.aligned.m8n8.x4.shared.b16 {%0,%1,%2,%3}, [%4];" \
        : "=r"(r0), "=r"(r1), "=r"(r2), "=r"(r3) : "r"(a))

// fp16-accumulator MMA: D,C packed 2 halves/reg
#define MMA_F16A(d, a, b0, b1) \
    asm volatile("mma.sync.aligned.m16n8k16.row.col.f16.f16.f16.f16 " \
        "{%0,%1}, {%2,%3,%4,%5}, {%6,%7}, {%0,%1};" \
        : "+r"((d)[0]), "+r"((d)[1]) \
        : "r"((a)[0]), "r"((a)[1]), "r"((a)[2]), "r"((a)[3]), "r"(b0), "r"(b1))

#define EX2F(u, t) asm("ex2.approx.ftz.f32 %0, %1;" : "=f"(u) : "f"(t))

__device__ __forceinline__ const float* row_ptr(const float* src, const float* tgt, int i) {
    return (i < NSRC) ? (src + (size_t)i * DIM) : (tgt + (size_t)(i - NSRC) * DIM);
}

// ---------------------------------------------------------------- prep kernels
// 256 blocks x 256 threads; block handles 32 rows (warp -> 4 rows).
// Fused: fp16 convert + per-row ||x||^2 + column sums.
__global__ void prep_kernel(const float* __restrict__ src, const float* __restrict__ tgt) {
    __shared__ float cs[DIM];
    int tid  = threadIdx.x;
    int wid  = tid >> 5;
    int lane = tid & 31;
    cs[tid] = 0.f;
    __syncthreads();

    float col_acc[8] = {0, 0, 0, 0, 0, 0, 0, 0};
    float sq_acc = 0.f;

    int rbase = blockIdx.x * 32 + wid * 4;
    for (int rr = 0; rr < 4; rr++) {
        int row = rbase + rr;
        const float4* p4 = (const float4*)row_ptr(src, tgt, row);
        float s = 0.f;
#pragma unroll
        for (int t = 0; t < 2; t++) {
            float4 v = p4[lane + t * 32];
            float x[4] = {v.x, v.y, v.z, v.w};
            uint32_t hb[4];
#pragma unroll
            for (int k = 0; k < 4; k++) {
                s += x[k] * x[k];
                col_acc[t * 4 + k] += x[k];
                hb[k] = (uint32_t)__half_as_ushort(__float2half_rn(x[k]));
            }
            size_t q = (size_t)row * 64 + lane + t * 32;   // uint2 index (4 halves)
            ((uint2*)g_h)[q] = make_uint2(hb[0] | (hb[1] << 16), hb[2] | (hb[3] << 16));
        }
#pragma unroll
        for (int o = 16; o > 0; o >>= 1) s += __shfl_xor_sync(0xffffffffu, s, o);
        if (lane == 0) { g_sq[row] = s; sq_acc += s; }
    }
    if (lane == 0) atomicAdd(&g_sumsq, (double)sq_acc);

#pragma unroll
    for (int t = 0; t < 2; t++)
#pragma unroll
        for (int k = 0; k < 4; k++)
            atomicAdd(&cs[t * 128 + lane * 4 + k], col_acc[t * 4 + k]);
    __syncthreads();
    atomicAdd(&g_colsum[tid], (double)cs[tid]);
}

__global__ void finalize_kernel() {
    __shared__ double red[DIM];
    int t = threadIdx.x;
    double c = g_colsum[t];
    red[t] = c * c;
    __syncthreads();
    for (int o = 128; o > 0; o >>= 1) {
        if (t < o) red[t] += red[t + o];
        __syncthreads();
    }
    if (t == 0) {
        double n = (double)NPTS;
        double sumL2 = 2.0 * n * g_sumsq - 2.0 * red[0];
        double bw = sumL2 / (n * n - n) / 4.0;   // / KERNEL_MUL^(KERNEL_NUM//2)
        g_c = (float)(-1.0 / (16.0 * bw * 0.6931471805599453));
    }
}

// ---------------------------------------------------------------- main tile kernel
// 256 threads, 8 warps (2x4), warp tile 64x32, CTA tile 128x128; 2 CTAs/SM.
// K chunk = 64: smem arrays per stage: A, B; each 128 rows x 144B (64 fp16 + 16 pad)
#define STRIDE_B    144
#define ARR_BYTES   (128 * STRIDE_B)        // 18432
#define STAGE_BYTES (2 * ARR_BYTES)         // 36864
#define NSTAGE      3
#define NCHUNK      4
#define DYN_SMEM    (NSTAGE * STAGE_BYTES)  // 110592

__global__ void __launch_bounds__(256, 2)
mmd_mma_kernel() {
    extern __shared__ char dsmem[];
    __shared__ float red[8];
    __shared__ float sqa_s[TILE];
    __shared__ float sqb_s[TILE];

    uint32_t dyn_u = smem_u32(dsmem);
    int tid  = threadIdx.x;
    int wid  = tid >> 5;
    int lane = tid & 31;
    int wm   = wid & 1;       // 2 warp-rows of 64
    int wn   = wid >> 1;      // 4 warp-cols of 32

    // decode linear block id -> (bi, bj), bi <= bj
    int b = blockIdx.x;
    float fb = (float)b;
    int bi = (int)((2.0f * NT + 1.0f - sqrtf((2.0f * NT + 1.0f) * (2.0f * NT + 1.0f) - 8.0f * fb)) * 0.5f);
    if (bi < 0) bi = 0;
    if (bi >= NT) bi = NT - 1;
#define TRI_START(i) ((i) * NT - (i) * ((i) - 1) / 2)
    while (bi + 1 < NT && TRI_START(bi + 1) <= b) bi++;
    while (bi > 0 && TRI_START(bi) > b) bi--;
    int bj = bi + (b - TRI_START(bi));
#undef TRI_START
    int row0 = bi * TILE;
    int col0 = bj * TILE;

    if (tid < TILE) {
        sqa_s[tid] = g_sq[row0 + tid];
        sqb_s[tid] = g_sq[col0 + tid];
    }

    const char* gbase[2];
    gbase[0] = (const char*)(g_h + (size_t)row0 * DIM);   // A
    gbase[1] = (const char*)(g_h + (size_t)col0 * DIM);   // B

    uint32_t acc[4][4][2];    // fp16x2 accumulators
#pragma unroll
    for (int mi = 0; mi < 4; mi++)
#pragma unroll
        for (int ni = 0; ni < 4; ni++) {
            acc[mi][ni][0] = 0u;
            acc[mi][ni][1] = 0u;
        }

    // loader: chunk c = k bytes [c*128, c*128+128); 2048 x 16B; 256 threads -> 8 each
#define ISSUE_LOADS(c, s) do { \
    _Pragma("unroll") \
    for (int i = 0; i < 8; i++) { \
        int arr = i >> 2; \
        int rem = tid + (i & 3) * 256;      /* 0..1023 */ \
        int row = rem >> 3; \
        int q   = rem & 7; \
        const char* srcp = gbase[arr] + (size_t)row * 512 + (c) * 128 + q * 16; \
        uint32_t dst = dyn_u + (s) * STAGE_BYTES + arr * ARR_BYTES + row * STRIDE_B + q * 16; \
        CP_ASYNC16(dst, srcp); \
    } \
    CP_COMMIT(); \
} while (0)

    // ldmatrix lane-address components
    int a_m    = lane >> 3;
    int a_rofs = ((a_m & 1) << 3) + (lane & 7);
    int a_koff = (a_m >> 1) << 4;
    int b_nofs = ((a_m >> 1) << 3) + (lane & 7);
    int b_koff = (a_m & 1) << 4;

    // fragment loader (double-buffered)
#define LOAD_FRAGS(buf, stage_u, ks) do { \
    _Pragma("unroll") \
    for (int mi = 0; mi < 4; mi++) { \
        int r = wm * 64 + mi * 16 + a_rofs; \
        uint32_t ad = (stage_u) + r * STRIDE_B + (ks) * 32 + a_koff; \
        LDSM_X4(Af[buf][mi][0], Af[buf][mi][1], Af[buf][mi][2], Af[buf][mi][3], ad); \
    } \
    _Pragma("unroll") \
    for (int pi = 0; pi < 2; pi++) { \
        int nl = wn * 32 + pi * 16 + b_nofs; \
        uint32_t bd = (stage_u) + ARR_BYTES + nl * STRIDE_B + (ks) * 32 + b_koff; \
        LDSM_X4(Bf[buf][pi][0], Bf[buf][pi][1], Bf[buf][pi][2], Bf[buf][pi][3], bd); \
    } \
} while (0)

#define DO_MMAS(buf) do { \
    _Pragma("unroll") \
    for (int mi = 0; mi < 4; mi++) { \
        _Pragma("unroll") \
        for (int ni = 0; ni < 4; ni++) { \
            int pi = ni >> 1, h = (ni & 1) * 2; \
            MMA_F16A(acc[mi][ni], Af[buf][mi], Bf[buf][pi][h], Bf[buf][pi][h + 1]); \
        } \
    } \
} while (0)

    uint32_t Af[2][4][4], Bf[2][2][4];

    ISSUE_LOADS(0, 0);
    ISSUE_LOADS(1, 1);

    for (int c = 0; c < NCHUNK; c++) {
        CP_WAIT1();           // chunk c resident
        __syncthreads();      // all warps past chunk c-1 compute; stage (c+2)%3 free
        if (c + 2 < NCHUNK) ISSUE_LOADS(c + 2, (c + 2) % NSTAGE);
        else CP_COMMIT();     // empty group keeps wait_group accounting exact

        uint32_t stage_u = dyn_u + (c % NSTAGE) * STAGE_BYTES;
        LOAD_FRAGS(0, stage_u, 0);
#pragma unroll
        for (int ks = 0; ks < 4; ks++) {
            int cur = ks & 1;
            if (ks < 3) LOAD_FRAGS(cur ^ 1, stage_u, ks + 1);
            DO_MMAS(cur);
        }
        // no trailing sync: next chunk's top barrier orders reads before refill
    }

    // ---------------- epilogue (fp32 exp, fp16x2 powers/sums) ----------------
    // element map: row = wm*64+mi*16 + lane/4 + (p)*8 ; col = wn*32+ni*8 + (lane%4)*2 + {0,1}
    float cexp = g_c;
    float m2c  = -2.f * cexp;
    int rlo = lane >> 2;
    int cl0 = (lane & 3) * 2;

    float tB0[4], tB1[4];
#pragma unroll
    for (int ni = 0; ni < 4; ni++) {
        tB0[ni] = cexp * sqb_s[wn * 32 + ni * 8 + cl0];
        tB1[ni] = cexp * sqb_s[wn * 32 + ni * 8 + cl0 + 1];
    }

    float s = 0.f;
#pragma unroll
    for (int mi = 0; mi < 4; mi++) {
        float tA[2];
        tA[0] = cexp * sqa_s[wm * 64 + mi * 16 + rlo];
        tA[1] = cexp * sqa_s[wm * 64 + mi * 16 + rlo + 8];
        __half2 s2 = __float2half2_rn(0.f);
#pragma unroll
        for (int ni = 0; ni < 4; ni++) {
#pragma unroll
            for (int p = 0; p < 2; p++) {
                float2 d = __half22float2(*(__half2*)&acc[mi][ni][p]);
                float t0 = fmaf(d.x, m2c, tA[p] + tB0[ni]);
                float t1 = fmaf(d.y, m2c, tA[p] + tB1[ni]);
                float u0, u1;
                EX2F(u0, t0);
                EX2F(u1, t1);
                __half2 u   = __floats2half2_rn(u0, u1);   // u in [0,1]: unbiased RN pack
                __half2 u2  = __hmul2(u, u);
                __half2 u4  = __hmul2(u2, u2);
                __half2 u8  = __hmul2(u4, u4);
                __half2 u16 = __hmul2(u8, u8);
                __half2 sm  = __hadd2(__hadd2(__hadd2(u, u2), __hadd2(u4, u8)), u16);
                s2 = __hadd2(s2, sm);
            }
        }
        float2 f = __half22float2(s2);
        s += f.x + f.y;
    }

    // warp-shuffle reduce, then tiny cross-warp fold
#pragma unroll
    for (int o = 16; o > 0; o >>= 1) s += __shfl_xor_sync(0xffffffffu, s, o);
    if (lane == 0) red[wid] = s;
    __syncthreads();
    if (tid == 0) {
        float t = 0.f;
#pragma unroll
        for (int i = 0; i < 8; i++) t += red[i];
        float w  = (bi == bj) ? 1.f : 2.f;
        float sr = (row0 < NSRC) ? 1.f : -1.f;
        float sc = (col0 < NSRC) ? 1.f : -1.f;
        atomicAdd(&g_acc, (double)(t * w * sr * sc));
    }
}

// Writes result and re-zeros accumulators so the next graph replay starts clean.
__global__ void writeout_kernel(float* out) {
    int t = threadIdx.x;
    if (t == 0) out[0] = (float)(g_acc / ((double)NSRC * (double)NSRC));
    if (t < DIM) g_colsum[t] = 0.0;
    if (t == 0) { g_sumsq = 0.0; g_acc = 0.0; }
}

// ---------------------------------------------------------------- launch
extern "C" void kernel_launch(void* const* d_in, const int* in_sizes, int n_in,
                              void* d_out, int out_size) {
    const float* src = (const float*)d_in[0];
    const float* tgt = (const float*)d_in[1];
    float* out = (float*)d_out;

    cudaFuncSetAttribute(mmd_mma_kernel, cudaFuncAttributeMaxDynamicSharedMemorySize, DYN_SMEM);

    prep_kernel<<<NPTS / 32, 256>>>(src, tgt);     // fp16 convert + norms + colsums fused
    finalize_kernel<<<1, 256>>>();
    mmd_mma_kernel<<<NBLK, 256, DYN_SMEM>>>();
    writeout_kernel<<<1, 256>>>(out);
}